// round 1
// baseline (speedup 1.0000x reference)
#include <cuda_runtime.h>

#define PV   113
#define DIM  128
#define NH   4
#define DHD  32
#define HID  512
#define NCOMBO 226
#define NPAIR (PV*PV)      // 12769
#define NTOK  (NPAIR*2)    // 25538

// ---------------- device scratch (static, no allocs) ----------------
__device__ float g_OW1[NH*DHD*HID];     // (h*32+i)*512 + j
__device__ float g_OU [NH*DHD*PV];      // (h*32+i)*113 + p
__device__ float g_W2U[HID*DIM];        // j*128 + n  (n>=113 zero-padded)
__device__ float g_b2u[PV];
__device__ float g_qk [2*NCOMBO*DIM];   // (sel*226+c)*128 + (h*32+i), sel: 0=q 1=k
__device__ float g_EW1[NCOMBO*HID];
__device__ float g_EU [NCOMBO*PV];
__device__ float g_AW1[NCOMBO*NH*HID];  // (c*4+h)*512 + j
__device__ float g_AU [NCOMBO*NH*PV];   // (c*4+h)*113 + p
__device__ float g_hrelu[(size_t)NTOK*HID];  // 52 MB
__device__ float g_base [(size_t)NPAIR*226];
__device__ float g_table[(size_t)NPAIR*226];

// ---------------- packed f32x2 helpers (Blackwell) ----------------
__device__ __forceinline__ unsigned long long pack2(float lo, float hi){
    unsigned long long r;
    asm("mov.b64 %0, {%1, %2};" : "=l"(r) : "f"(lo), "f"(hi));
    return r;
}
__device__ __forceinline__ void fma2(unsigned long long &d, unsigned long long a, unsigned long long b){
    asm("fma.rn.f32x2 %0, %1, %2, %0;" : "+l"(d) : "l"(a), "l"(b));
}
__device__ __forceinline__ void unpack2(float &lo, float &hi, unsigned long long v){
    asm("mov.b64 {%0, %1}, %2;" : "=f"(lo), "=f"(hi) : "l"(v));
}

// ---------------- A1: fold weights ----------------
// outputs: OW1 (65536), OU (14464), W2U padded (65536), b2u (113) -> 145649
__global__ void kA1(const float* __restrict__ WO, const float* __restrict__ W1,
                    const float* __restrict__ W2, const float* __restrict__ b2,
                    const float* __restrict__ WU){
    int t = blockIdx.x*256 + threadIdx.x;
    if (t < 65536) {
        int j = t & 511, hi = t >> 9;
        const float* wo = WO + hi*DIM;
        float s = 0.f;
        #pragma unroll 8
        for (int d=0; d<DIM; d++) s += wo[d]*W1[d*HID + j];
        g_OW1[t] = s;
    } else if (t < 80000) {
        int u = t - 65536; int p = u % PV; int hi = u / PV;
        const float* wo = WO + hi*DIM; const float* wu = WU + p*DIM;
        float s = 0.f;
        #pragma unroll 8
        for (int d=0; d<DIM; d++) s += wo[d]*wu[d];
        g_OU[u] = s;
    } else if (t < 145536) {
        int u = t - 80000; int n = u & 127; int j = u >> 7;
        float s = 0.f;
        if (n < PV) {
            const float* w2 = W2 + j*DIM; const float* wu = WU + n*DIM;
            #pragma unroll 8
            for (int d=0; d<DIM; d++) s += w2[d]*wu[d];
        }
        g_W2U[u] = s;
    } else if (t < 145649) {
        int p = t - 145536;
        const float* wu = WU + p*DIM;
        float s = 0.f;
        #pragma unroll 8
        for (int d=0; d<DIM; d++) s += b2[d]*wu[d];
        g_b2u[p] = s;
    }
}

// ---------------- A2: per-(token,pos) combo tables ----------------
__global__ void kA2(const float* __restrict__ tok_emb, const float* __restrict__ pos_emb,
                    const float* __restrict__ WQ, const float* __restrict__ WK,
                    const float* __restrict__ WV, const float* __restrict__ W1,
                    const float* __restrict__ b1, const float* __restrict__ WU){
    __shared__ float e[DIM];
    __shared__ float vv[DIM];
    const int c = blockIdx.x;
    const int tk = c >> 1, pos = c & 1;
    const int tid = threadIdx.x;
    if (tid < DIM) e[tid] = tok_emb[tk*DIM + tid] + pos_emb[pos*DIM + tid];
    __syncthreads();

    // q / k / v : 384 dot products of length 128
    for (int o = tid; o < 384; o += 256) {
        int sel = o >> 7; int idx = o & 127;
        const float* W = (sel==0) ? WQ : ((sel==1) ? WK : WV);
        int h = idx >> 5, i = idx & 31;
        float s = 0.f;
        #pragma unroll 8
        for (int d=0; d<DIM; d++) s += e[d]*W[(h*DIM + d)*DHD + i];
        if (sel < 2) g_qk[(sel*NCOMBO + c)*DIM + idx] = s;
        else         vv[idx] = s;
    }
    __syncthreads();

    // EW1
    for (int j = tid; j < HID; j += 256) {
        float s = b1[j];
        #pragma unroll 8
        for (int d=0; d<DIM; d++) s += e[d]*W1[d*HID + j];
        g_EW1[c*HID + j] = s;
    }
    // EU (+b2u folded)
    if (tid < PV) {
        const float* wu = WU + tid*DIM;
        float s = g_b2u[tid];
        #pragma unroll 8
        for (int d=0; d<DIM; d++) s += e[d]*wu[d];
        g_EU[c*PV + tid] = s;
    }
    // AW1
    for (int o = tid; o < NH*HID; o += 256) {
        int h = o >> 9; int j = o & 511;
        float s = 0.f;
        #pragma unroll
        for (int i=0; i<DHD; i++) s += vv[h*DHD + i]*g_OW1[(h*DHD + i)*HID + j];
        g_AW1[(c*NH + h)*HID + j] = s;
    }
    // AU
    for (int o = tid; o < NH*PV; o += 256) {
        int h = o / PV; int p = o % PV;
        float s = 0.f;
        #pragma unroll
        for (int i=0; i<DHD; i++) s += vv[h*DHD + i]*g_OU[(h*DHD + i)*PV + p];
        g_AU[(c*NH + h)*PV + p] = s;
    }
}

// ---------------- B1: per-pair pattern, preact->relu, base logits ----------------
__global__ void kB1(){
    const int pair = blockIdx.x;
    const int a = pair / PV, b = pair % PV;
    const int ca = a*2, cb = b*2 + 1;
    __shared__ float sc[16];
    __shared__ float pat[16];  // [h*4 + qi*2 + si]
    const int tid = threadIdx.x;

    if (tid < 16) {
        int h = tid >> 2, qi = (tid >> 1) & 1, si = tid & 1;
        int cq = qi ? cb : ca;
        int cs = si ? cb : ca;
        const float* q = g_qk + (0*NCOMBO + cq)*DIM + h*DHD;
        const float* k = g_qk + (1*NCOMBO + cs)*DIM + h*DHD;
        float s = 0.f;
        #pragma unroll
        for (int i=0; i<DHD; i++) s += q[i]*k[i];
        sc[tid] = s * 0.17677669529663687f; // 1/sqrt(32)
    }
    __syncthreads();
    if (tid < 8) {
        int base = tid*2;
        float s0 = sc[base], s1 = sc[base+1];
        float m = fmaxf(s0, s1);
        float e0 = __expf(s0 - m), e1 = __expf(s1 - m);
        float p0 = e0/(e0 + e1);
        pat[base]   = 0.5f + 0.5f*p0;
        pat[base+1] = 0.5f + 0.5f*(1.0f - p0);
    }
    __syncthreads();

    // preact + relu for both tokens (reuse AW1 loads across tokens)
    #pragma unroll
    for (int r=0; r<2; r++) {
        int j = tid + r*256;
        float pr0 = g_EW1[ca*HID + j];
        float pr1 = g_EW1[cb*HID + j];
        #pragma unroll
        for (int h=0; h<NH; h++){
            float Aa = g_AW1[(ca*NH + h)*HID + j];
            float Ab = g_AW1[(cb*NH + h)*HID + j];
            pr0 += pat[h*4+0]*Aa + pat[h*4+1]*Ab;
            pr1 += pat[h*4+2]*Aa + pat[h*4+3]*Ab;
        }
        g_hrelu[((size_t)pair*2 + 0)*HID + j] = fmaxf(pr0, 0.f);
        g_hrelu[((size_t)pair*2 + 1)*HID + j] = fmaxf(pr1, 0.f);
    }
    // base logits (everything except the MLP GEMM)
    if (tid < 226) {
        int qi = tid / PV, p = tid % PV;
        int cq = qi ? cb : ca;
        float s = g_EU[cq*PV + p];
        #pragma unroll
        for (int h=0; h<NH; h++){
            s += pat[h*4 + qi*2 + 0]*g_AU[(ca*NH + h)*PV + p]
               + pat[h*4 + qi*2 + 1]*g_AU[(cb*NH + h)*PV + p];
        }
        g_base[(size_t)pair*226 + tid] = s;
    }
}

// ---------------- B2: table = base + hrelu @ W2U  (M=25538,K=512,N=113) ----------------
// BM=128, BN=128(pad), BK=16, 256 threads, 8x8 thread tile, packed f32x2 FMA
__global__ void __launch_bounds__(256) kB2(){
    __shared__ float As[16][128];
    __shared__ float Bs[16][128];
    const int tid = threadIdx.x;
    const int bm  = blockIdx.x * 128;
    const int tx  = tid & 15;   // n-group
    const int ty  = tid >> 4;   // m-group
    unsigned long long acc[8][4];
    #pragma unroll
    for (int m=0;m<8;m++){
        #pragma unroll
        for (int n=0;n<4;n++) acc[m][n] = 0ULL;
    }
    const int arow = tid >> 1;
    const int acol = (tid & 1) * 8;
    const int gmL  = bm + arow;
    const float* aptr = g_hrelu + (size_t)gmL*HID + acol;
    const float* bptr = g_W2U + (tid >> 4)*DIM + (tid & 15)*8;

    for (int kk=0; kk<HID; kk+=16){
        float4 a0 = make_float4(0,0,0,0), a1 = make_float4(0,0,0,0);
        if (gmL < NTOK){
            a0 = *(const float4*)(aptr + kk);
            a1 = *(const float4*)(aptr + kk + 4);
        }
        float4 b0 = *(const float4*)(bptr + kk*DIM);
        float4 b1 = *(const float4*)(bptr + kk*DIM + 4);
        __syncthreads();
        As[acol+0][arow]=a0.x; As[acol+1][arow]=a0.y; As[acol+2][arow]=a0.z; As[acol+3][arow]=a0.w;
        As[acol+4][arow]=a1.x; As[acol+5][arow]=a1.y; As[acol+6][arow]=a1.z; As[acol+7][arow]=a1.w;
        *(float4*)&Bs[tid>>4][(tid&15)*8]     = b0;
        *(float4*)&Bs[tid>>4][(tid&15)*8 + 4] = b1;
        __syncthreads();
        #pragma unroll
        for (int k=0;k<16;k++){
            float4 av0 = *(const float4*)&As[k][ty*8];
            float4 av1 = *(const float4*)&As[k][ty*8+4];
            float4 bv0 = *(const float4*)&Bs[k][tx*8];
            float4 bv1 = *(const float4*)&Bs[k][tx*8+4];
            unsigned long long bp0 = pack2(bv0.x,bv0.y);
            unsigned long long bp1 = pack2(bv0.z,bv0.w);
            unsigned long long bp2 = pack2(bv1.x,bv1.y);
            unsigned long long bp3 = pack2(bv1.z,bv1.w);
            float am[8] = {av0.x,av0.y,av0.z,av0.w,av1.x,av1.y,av1.z,av1.w};
            #pragma unroll
            for (int m=0;m<8;m++){
                unsigned long long a2 = pack2(am[m],am[m]);
                fma2(acc[m][0],a2,bp0);
                fma2(acc[m][1],a2,bp1);
                fma2(acc[m][2],a2,bp2);
                fma2(acc[m][3],a2,bp3);
            }
        }
    }
    // epilogue: add base, write table
    #pragma unroll
    for (int m=0;m<8;m++){
        int gm = bm + ty*8 + m;
        if (gm >= NTOK) continue;
        #pragma unroll
        for (int n2=0;n2<4;n2++){
            float lo, hi; unpack2(lo, hi, acc[m][n2]);
            int n = tx*8 + n2*2;
            if (n   < PV) g_table[(size_t)gm*PV + n]   = g_base[(size_t)gm*PV + n]   + lo;
            if (n+1 < PV) g_table[(size_t)gm*PV + n+1] = g_base[(size_t)gm*PV + n+1] + hi;
        }
    }
}

// ---------------- G: gather table rows into output ----------------
__global__ void kG(const int* __restrict__ x, float* __restrict__ out, int B){
    int ex = blockIdx.x*8 + (threadIdx.x >> 5);
    if (ex >= B) return;
    int lane = threadIdx.x & 31;
    int a = x[ex*2], b = x[ex*2+1];
    const float2* src = (const float2*)(g_table + (size_t)(a*PV + b)*226);
    float2* dst = (float2*)(out + (size_t)ex*226);
    #pragma unroll
    for (int i=0;i<4;i++){
        int idx = lane + i*32;
        if (idx < PV) dst[idx] = src[idx];   // 113 float2 = 226 floats
    }
}

// ---------------- launch ----------------
extern "C" void kernel_launch(void* const* d_in, const int* in_sizes, int n_in,
                              void* d_out, int out_size){
    const int*   x   = (const int*)  d_in[0];
    const float* tok = (const float*)d_in[1];
    const float* pos = (const float*)d_in[2];
    const float* WQ  = (const float*)d_in[3];
    const float* WK  = (const float*)d_in[4];
    const float* WV  = (const float*)d_in[5];
    const float* WO  = (const float*)d_in[6];
    const float* W1  = (const float*)d_in[7];
    const float* b1  = (const float*)d_in[8];
    const float* W2  = (const float*)d_in[9];
    const float* b2  = (const float*)d_in[10];
    const float* WU  = (const float*)d_in[11];
    float* out = (float*)d_out;
    const int B = in_sizes[0] / 2;

    kA1<<<569, 256>>>(WO, W1, W2, b2, WU);
    kA2<<<NCOMBO, 256>>>(tok, pos, WQ, WK, WV, W1, b1, WU);
    kB1<<<NPAIR, 256>>>();
    kB2<<<(NTOK + 127)/128, 256>>>();
    kG<<<(B + 7)/8, 256>>>(x, out, B);
}

// round 2
// speedup vs baseline: 1.0128x; 1.0128x over previous
#include <cuda_runtime.h>

#define PV   113
#define DIM  128
#define NH   4
#define DHD  32
#define HID  512
#define NCOMBO 226
#define NPAIR (PV*PV)      // 12769
#define NTOK  (NPAIR*2)    // 25538
#define PPB   64           // pairs per GEMM block

typedef unsigned long long ull;

// ---------------- device scratch (static, zero-initialized) ----------------
__device__ float g_OW1[NH*DHD*HID];
__device__ float g_OU [NH*DHD*PV];
__device__ float g_W2U[HID*DIM];             // j*128 + n (n>=113 zero)
__device__ float g_b2u[PV];
__device__ float g_qk [2*NCOMBO*DIM];
__device__ float g_EW1[(NCOMBO+2)*HID];      // padded for OOB pair tiles
__device__ float g_EU [NCOMBO*PV];
__device__ float g_AW1[(NCOMBO+2)*NH*HID];   // padded
__device__ float g_AU [NCOMBO*NH*PV];
__device__ float g_pat[(NPAIR+PPB)*16];      // padded
__device__ float g_base [(size_t)NTOK*PV];
__device__ float g_table[(size_t)NTOK*PV];

// ---------------- packed f32x2 helpers ----------------
__device__ __forceinline__ ull pack2(float lo, float hi){
    ull r; asm("mov.b64 %0, {%1, %2};" : "=l"(r) : "f"(lo), "f"(hi)); return r;
}
__device__ __forceinline__ void fma2(ull &d, ull a, ull b){
    asm("fma.rn.f32x2 %0, %1, %2, %0;" : "+l"(d) : "l"(a), "l"(b));
}
__device__ __forceinline__ void unpack2(float &lo, float &hi, ull v){
    asm("mov.b64 {%0, %1}, %2;" : "=f"(lo), "=f"(hi) : "l"(v));
}

// ---------------- A1: fold weights ----------------
__global__ void kA1(const float* __restrict__ WO, const float* __restrict__ W1,
                    const float* __restrict__ W2, const float* __restrict__ b2,
                    const float* __restrict__ WU){
    int t = blockIdx.x*256 + threadIdx.x;
    if (t < 65536) {
        int j = t & 511, hi = t >> 9;
        const float* wo = WO + hi*DIM;
        float s = 0.f;
        #pragma unroll 8
        for (int d=0; d<DIM; d++) s += wo[d]*W1[d*HID + j];
        g_OW1[t] = s;
    } else if (t < 80000) {
        int u = t - 65536; int p = u % PV; int hi = u / PV;
        const float* wo = WO + hi*DIM; const float* wu = WU + p*DIM;
        float s = 0.f;
        #pragma unroll 8
        for (int d=0; d<DIM; d++) s += wo[d]*wu[d];
        g_OU[u] = s;
    } else if (t < 145536) {
        int u = t - 80000; int n = u & 127; int j = u >> 7;
        float s = 0.f;
        if (n < PV) {
            const float* w2 = W2 + j*DIM; const float* wu = WU + n*DIM;
            #pragma unroll 8
            for (int d=0; d<DIM; d++) s += w2[d]*wu[d];
        }
        g_W2U[u] = s;
    } else if (t < 145649) {
        int p = t - 145536;
        const float* wu = WU + p*DIM;
        float s = 0.f;
        #pragma unroll 8
        for (int d=0; d<DIM; d++) s += b2[d]*wu[d];
        g_b2u[p] = s;
    }
}

// ---------------- A2: per-(token,pos) combo tables ----------------
__global__ void kA2(const float* __restrict__ tok_emb, const float* __restrict__ pos_emb,
                    const float* __restrict__ WQ, const float* __restrict__ WK,
                    const float* __restrict__ WV, const float* __restrict__ W1,
                    const float* __restrict__ b1, const float* __restrict__ WU){
    __shared__ float e[DIM];
    __shared__ float vv[DIM];
    const int c = blockIdx.x;
    const int tk = c >> 1, pos = c & 1;
    const int tid = threadIdx.x;
    if (tid < DIM) e[tid] = tok_emb[tk*DIM + tid] + pos_emb[pos*DIM + tid];
    __syncthreads();

    for (int o = tid; o < 384; o += 256) {
        int sel = o >> 7; int idx = o & 127;
        const float* W = (sel==0) ? WQ : ((sel==1) ? WK : WV);
        int h = idx >> 5, i = idx & 31;
        float s = 0.f;
        #pragma unroll 8
        for (int d=0; d<DIM; d++) s += e[d]*W[(h*DIM + d)*DHD + i];
        if (sel < 2) g_qk[(sel*NCOMBO + c)*DIM + idx] = s;
        else         vv[idx] = s;
    }
    __syncthreads();

    for (int j = tid; j < HID; j += 256) {
        float s = b1[j];
        #pragma unroll 8
        for (int d=0; d<DIM; d++) s += e[d]*W1[d*HID + j];
        g_EW1[c*HID + j] = s;
    }
    if (tid < PV) {
        const float* wu = WU + tid*DIM;
        float s = g_b2u[tid];
        #pragma unroll 8
        for (int d=0; d<DIM; d++) s += e[d]*wu[d];
        g_EU[c*PV + tid] = s;
    }
    for (int o = tid; o < NH*HID; o += 256) {
        int h = o >> 9; int j = o & 511;
        float s = 0.f;
        #pragma unroll
        for (int i=0; i<DHD; i++) s += vv[h*DHD + i]*g_OW1[(h*DHD + i)*HID + j];
        g_AW1[(c*NH + h)*HID + j] = s;
    }
    for (int o = tid; o < NH*PV; o += 256) {
        int h = o / PV; int p = o % PV;
        float s = 0.f;
        #pragma unroll
        for (int i=0; i<DHD; i++) s += vv[h*DHD + i]*g_OU[(h*DHD + i)*PV + p];
        g_AU[(c*NH + h)*PV + p] = s;
    }
}

// ---------------- B1b: pattern + base logits (no hrelu) ----------------
__global__ void kB1b(){
    const int pair = blockIdx.x;
    const int a = pair / PV, b = pair % PV;
    const int ca = a*2, cb = b*2 + 1;
    __shared__ float sc[16];
    __shared__ float pat[16];  // [h*4 + qi*2 + si]
    const int tid = threadIdx.x;

    if (tid < 16) {
        int h = tid >> 2, qi = (tid >> 1) & 1, si = tid & 1;
        int cq = qi ? cb : ca;
        int cs = si ? cb : ca;
        const float* q = g_qk + (0*NCOMBO + cq)*DIM + h*DHD;
        const float* k = g_qk + (1*NCOMBO + cs)*DIM + h*DHD;
        float s = 0.f;
        #pragma unroll
        for (int i=0; i<DHD; i++) s += q[i]*k[i];
        sc[tid] = s * 0.17677669529663687f;
    }
    __syncthreads();
    if (tid < 8) {
        int base = tid*2;
        float s0 = sc[base], s1 = sc[base+1];
        float m = fmaxf(s0, s1);
        float e0 = __expf(s0 - m), e1 = __expf(s1 - m);
        float p0 = e0/(e0 + e1);
        pat[base]   = 0.5f + 0.5f*p0;
        pat[base+1] = 0.5f + 0.5f*(1.0f - p0);
    }
    __syncthreads();
    if (tid < 16) g_pat[pair*16 + tid] = pat[tid];

    if (tid < 226) {
        int qi = tid / PV, p = tid % PV;
        int cq = qi ? cb : ca;
        float s = g_EU[cq*PV + p];
        #pragma unroll
        for (int h=0; h<NH; h++){
            s += pat[h*4 + qi*2 + 0]*g_AU[(ca*NH + h)*PV + p]
               + pat[h*4 + qi*2 + 1]*g_AU[(cb*NH + h)*PV + p];
        }
        g_base[(size_t)(pair*2 + qi)*PV + p] = s;
    }
}

// ---------------- FB2: fused preact/relu + GEMM + base-add ----------------
// grid (200, 2): 64 pairs (128 rows) x 64-col half. 128 threads, 8x8 tile.
__global__ void __launch_bounds__(128, 4) kFB2(){
    __shared__ float As[16][132];
    __shared__ float Bs[16][64];
    __shared__ float sPatT[16][64];   // transposed: [i][local pair]
    const int t = threadIdx.x;
    const int p0 = blockIdx.x * PPB;
    const int nbase = blockIdx.y * 64;

    // stage pat transposed (g_pat is padded, no guard needed)
    {
        int lp0 = t & 63, i0 = (t >> 6) * 8;
        const float* src = g_pat + (size_t)(p0 + lp0)*16 + i0;
        float4 v0 = *(const float4*)(src);
        float4 v1 = *(const float4*)(src + 4);
        sPatT[i0+0][lp0]=v0.x; sPatT[i0+1][lp0]=v0.y; sPatT[i0+2][lp0]=v0.z; sPatT[i0+3][lp0]=v0.w;
        sPatT[i0+4][lp0]=v1.x; sPatT[i0+5][lp0]=v1.y; sPatT[i0+6][lp0]=v1.z; sPatT[i0+7][lp0]=v1.w;
    }

    const int lp = t >> 1, half = t & 1;
    const int pair = p0 + lp;
    const int a = pair / PV, b = pair % PV;
    const int ca = 2*a, cb = 2*b + 1;
    const float* pEa = g_EW1 + ca*HID + half*8;
    const float* pEb = g_EW1 + cb*HID + half*8;
    const float* pAa = g_AW1 + (ca*NH)*HID + half*8;
    const float* pAb = g_AW1 + (cb*NH)*HID + half*8;

    const int brow = t >> 3;          // 0..15
    const int bc   = (t & 7) * 8;     // 0..56
    const float* pB = g_W2U + brow*DIM + nbase + bc;

    const int ty = t >> 3;            // 0..15 (m-group of 8)
    const int tx = t & 7;             // 0..7  (n-group of 8)

    ull acc[8][4];
    #pragma unroll
    for (int m=0;m<8;m++){ acc[m][0]=0ULL; acc[m][1]=0ULL; acc[m][2]=0ULL; acc[m][3]=0ULL; }

    __syncthreads();

    for (int kk = 0; kk < HID; kk += 16) {
        // ---- compute hrelu tile fragment (2 rows x 8 cols) ----
        float pv[16];
        #pragma unroll
        for (int i=0;i<16;i++) pv[i] = sPatT[i][lp];

        float4 e0 = *(const float4*)(pEa + kk);
        float4 e1 = *(const float4*)(pEa + kk + 4);
        float4 f0 = *(const float4*)(pEb + kk);
        float4 f1 = *(const float4*)(pEb + kk + 4);
        float pr0[8] = {e0.x,e0.y,e0.z,e0.w,e1.x,e1.y,e1.z,e1.w};
        float pr1[8] = {f0.x,f0.y,f0.z,f0.w,f1.x,f1.y,f1.z,f1.w};
        #pragma unroll
        for (int h=0; h<NH; h++){
            float4 A0 = *(const float4*)(pAa + h*HID + kk);
            float4 A1 = *(const float4*)(pAa + h*HID + kk + 4);
            float4 B0 = *(const float4*)(pAb + h*HID + kk);
            float4 B1 = *(const float4*)(pAb + h*HID + kk + 4);
            float aa[8] = {A0.x,A0.y,A0.z,A0.w,A1.x,A1.y,A1.z,A1.w};
            float bb[8] = {B0.x,B0.y,B0.z,B0.w,B1.x,B1.y,B1.z,B1.w};
            float w00 = pv[h*4+0], w01 = pv[h*4+1];
            float w10 = pv[h*4+2], w11 = pv[h*4+3];
            #pragma unroll
            for (int c=0;c<8;c++){
                pr0[c] += w00*aa[c] + w01*bb[c];
                pr1[c] += w10*aa[c] + w11*bb[c];
            }
        }
        float4 bv0 = *(const float4*)(pB + kk*DIM);
        float4 bv1 = *(const float4*)(pB + kk*DIM + 4);

        __syncthreads();
        #pragma unroll
        for (int c=0;c<8;c++){
            float2 v; v.x = fmaxf(pr0[c], 0.f); v.y = fmaxf(pr1[c], 0.f);
            *(float2*)&As[half*8 + c][2*lp] = v;
        }
        *(float4*)&Bs[brow][bc]   = bv0;
        *(float4*)&Bs[brow][bc+4] = bv1;
        __syncthreads();

        // ---- GEMM on the tile ----
        #pragma unroll
        for (int k=0;k<16;k++){
            float4 av0 = *(const float4*)&As[k][ty*8];
            float4 av1 = *(const float4*)&As[k][ty*8+4];
            ull bp0 = *(const ull*)&Bs[k][tx*8];
            ull bp1 = *(const ull*)&Bs[k][tx*8+2];
            ull bp2 = *(const ull*)&Bs[k][tx*8+4];
            ull bp3 = *(const ull*)&Bs[k][tx*8+6];
            float am[8] = {av0.x,av0.y,av0.z,av0.w,av1.x,av1.y,av1.z,av1.w};
            #pragma unroll
            for (int m=0;m<8;m++){
                ull a2 = pack2(am[m],am[m]);
                fma2(acc[m][0],a2,bp0);
                fma2(acc[m][1],a2,bp1);
                fma2(acc[m][2],a2,bp2);
                fma2(acc[m][3],a2,bp3);
            }
        }
    }

    // ---- epilogue: add base, write table ----
    #pragma unroll
    for (int m=0;m<8;m++){
        int gm = p0*2 + ty*8 + m;
        if (gm >= NTOK) continue;
        const float* bs = g_base + (size_t)gm*PV;
        float* ts = g_table + (size_t)gm*PV;
        #pragma unroll
        for (int np=0;np<4;np++){
            float lo, hi; unpack2(lo, hi, acc[m][np]);
            int n = nbase + tx*8 + np*2;
            if (n   < PV) ts[n]   = bs[n]   + lo;
            if (n+1 < PV) ts[n+1] = bs[n+1] + hi;
        }
    }
}

// ---------------- G: gather table rows into output ----------------
__global__ void kG(const int* __restrict__ x, float* __restrict__ out, int B){
    int ex = blockIdx.x*8 + (threadIdx.x >> 5);
    if (ex >= B) return;
    int lane = threadIdx.x & 31;
    int a = x[ex*2], b = x[ex*2+1];
    const float2* src = (const float2*)(g_table + (size_t)(a*PV + b)*226);
    float2* dst = (float2*)(out + (size_t)ex*226);
    #pragma unroll
    for (int i=0;i<4;i++){
        int idx = lane + i*32;
        if (idx < PV) dst[idx] = src[idx];
    }
}

// ---------------- launch ----------------
extern "C" void kernel_launch(void* const* d_in, const int* in_sizes, int n_in,
                              void* d_out, int out_size){
    const int*   x   = (const int*)  d_in[0];
    const float* tok = (const float*)d_in[1];
    const float* pos = (const float*)d_in[2];
    const float* WQ  = (const float*)d_in[3];
    const float* WK  = (const float*)d_in[4];
    const float* WV  = (const float*)d_in[5];
    const float* WO  = (const float*)d_in[6];
    const float* W1  = (const float*)d_in[7];
    const float* b1  = (const float*)d_in[8];
    const float* W2  = (const float*)d_in[9];
    const float* b2  = (const float*)d_in[10];
    const float* WU  = (const float*)d_in[11];
    float* out = (float*)d_out;
    const int B = in_sizes[0] / 2;

    kA1<<<569, 256>>>(WO, W1, W2, b2, WU);
    kA2<<<NCOMBO, 256>>>(tok, pos, WQ, WK, WV, W1, b1, WU);
    kB1b<<<NPAIR, 256>>>();
    dim3 g2((NPAIR + PPB - 1)/PPB, 2);
    kFB2<<<g2, 128>>>();
    kG<<<(B + 7)/8, 256>>>(x, out, B);
}